// round 1
// baseline (speedup 1.0000x reference)
#include <cuda_runtime.h>
#include <cuda_bf16.h>
#include <cstdint>

#define IN_DIM  128
#define OUT_DIM 128
#define NHEADS  4
#define NEG_SLOPE 0.2f

#define N_MAX 50000
#define E_MAX 1600000

// -------- device scratch (static: no allocation allowed) --------
__device__ float    g_hq   [N_MAX * NHEADS];
__device__ float    g_kact [N_MAX * NHEADS];
__device__ float    g_qagg [N_MAX * NHEADS];
__device__ unsigned g_mx   [N_MAX * NHEADS];
__device__ float    g_sm   [N_MAX * NHEADS];
__device__ float    g_hproj[(size_t)N_MAX * OUT_DIM];

// -------- helpers --------
__device__ __forceinline__ void red_add_v4(float* p, float a, float b, float c, float d) {
    asm volatile("red.global.add.v4.f32 [%0], {%1, %2, %3, %4};"
                 :: "l"(p), "f"(a), "f"(b), "f"(c), "f"(d) : "memory");
}

// monotone float<->uint mapping for atomicMax on floats (handles negatives)
__device__ __forceinline__ unsigned flipf(float f) {
    unsigned u = __float_as_uint(f);
    return (u & 0x80000000u) ? ~u : (u | 0x80000000u);
}
__device__ __forceinline__ float unflipf(unsigned u) {
    return __uint_as_float((u & 0x80000000u) ? (u & 0x7FFFFFFFu) : ~u);
}

// flip(-inf) = ~0xFF800000 = 0x007FFFFF
#define MX_INIT 0x007FFFFFu

// ================= kernel 0: init =================
__global__ __launch_bounds__(256) void init_kernel(float* __restrict__ out, int out_n, int nh) {
    int i = blockIdx.x * 256 + threadIdx.x;
    if (i < out_n) out[i] = 0.0f;
    if (i < nh) {
        g_qagg[i] = 0.0f;
        g_sm[i]   = 0.0f;
        g_mx[i]   = MX_INIT;
    }
}

// ================= kernel 1: projections =================
// block = 128 threads, handles NPB nodes. thread t owns output column t of h_proj.
#define NPB 16
__global__ __launch_bounds__(128) void proj_kernel(
    const float* __restrict__ x,
    const float* __restrict__ Wq, const float* __restrict__ Wk,
    const float* __restrict__ Wl, const float* __restrict__ bl, int N)
{
    __shared__ float xs[NPB * IN_DIM];
    const int t = threadIdx.x;
    const int base = blockIdx.x * NPB;
    const int nn = min(NPB, N - base);
    if (nn <= 0) return;

    // load x tile (coalesced float4)
    {
        const float4* xg = (const float4*)(x + (size_t)base * IN_DIM);
        float4* xs4 = (float4*)xs;
        const int tot4 = nn * (IN_DIM / 4);
        for (int i = t; i < tot4; i += 128) xs4[i] = xg[i];
    }
    __syncthreads();

    // per-head q/k projections: t = n2*8 + h  (h<4 -> Wq head h, else Wk head h-4)
    {
        const int n2 = t >> 3;
        const int h  = t & 7;
        if (n2 < nn) {
            const float* wrow = (h < 4) ? (Wq + h * IN_DIM) : (Wk + (h - 4) * IN_DIM);
            const float4* w4 = (const float4*)wrow;
            const float4* xr = (const float4*)(xs + n2 * IN_DIM);
            float d = 0.0f;
            #pragma unroll
            for (int k = 0; k < IN_DIM / 4; k++) {
                float4 w = w4[k]; float4 xv = xr[k];
                d += w.x * xv.x + w.y * xv.y + w.z * xv.z + w.w * xv.w;
            }
            const int node = base + n2;
            if (h < 4) g_hq[node * NHEADS + h] = d;
            else       g_kact[node * NHEADS + (h - 4)] = (d >= 0.0f) ? d : NEG_SLOPE * d;
        }
    }

    // big projection: acc[n] = dot(x[base+n], Wl[t])
    float acc[NPB];
    #pragma unroll
    for (int n = 0; n < NPB; n++) acc[n] = 0.0f;

    const float4* wl4 = (const float4*)(Wl + (size_t)t * IN_DIM);
    #pragma unroll 4
    for (int k = 0; k < IN_DIM / 4; k++) {
        float4 w = wl4[k];
        #pragma unroll
        for (int n = 0; n < NPB; n++) {
            float4 xv = ((const float4*)(xs + n * IN_DIM))[k];
            acc[n] += w.x * xv.x + w.y * xv.y + w.z * xv.z + w.w * xv.w;
        }
    }
    const float b = bl[t];
    for (int n = 0; n < nn; n++)
        g_hproj[(size_t)(base + n) * OUT_DIM + t] = acc[n] + b;
}

// ================= kernel 2: q_agg scatter =================
// q_agg[row] += h_q[col]  (4 floats, one vector red per edge)
__global__ __launch_bounds__(256) void qagg_kernel(
    const int* __restrict__ rows, const int* __restrict__ cols, int E)
{
    int e = blockIdx.x * 256 + threadIdx.x;
    if (e >= E) return;
    int r = rows[e];
    int c = cols[e];
    float4 v = ((const float4*)g_hq)[c];
    red_add_v4(g_qagg + (size_t)r * 4, v.x, v.y, v.z, v.w);
}

// ================= kernel 3: segment max of scores =================
__global__ __launch_bounds__(256) void smax_kernel(
    const int* __restrict__ rows, const int* __restrict__ cols, int E)
{
    int e = blockIdx.x * 256 + threadIdx.x;
    if (e >= E) return;
    int r = rows[e];
    int c = cols[e];
    float4 kv = ((const float4*)g_kact)[r];
    float4 qv = ((const float4*)g_qagg)[c];
    unsigned* m = g_mx + (size_t)r * 4;
    atomicMax(m + 0, flipf(kv.x * qv.x));
    atomicMax(m + 1, flipf(kv.y * qv.y));
    atomicMax(m + 2, flipf(kv.z * qv.z));
    atomicMax(m + 3, flipf(kv.w * qv.w));
}

// ================= kernel 4: segment sum of exp =================
__global__ __launch_bounds__(256) void ssum_kernel(
    const int* __restrict__ rows, const int* __restrict__ cols, int E)
{
    int e = blockIdx.x * 256 + threadIdx.x;
    if (e >= E) return;
    int r = rows[e];
    int c = cols[e];
    float4 kv = ((const float4*)g_kact)[r];
    float4 qv = ((const float4*)g_qagg)[c];
    uint4  mu = ((const uint4*)g_mx)[r];
    float e0 = __expf(kv.x * qv.x - unflipf(mu.x));
    float e1 = __expf(kv.y * qv.y - unflipf(mu.y));
    float e2 = __expf(kv.z * qv.z - unflipf(mu.z));
    float e3 = __expf(kv.w * qv.w - unflipf(mu.w));
    red_add_v4(g_sm + (size_t)r * 4, e0, e1, e2, e3);
}

// ================= kernel 5: weighted aggregation =================
// one warp per edge: compute alpha_mean, gather h_proj[col] (512B), vector-red into out[row]
__global__ __launch_bounds__(256) void aggregate_kernel(
    const int* __restrict__ rows, const int* __restrict__ cols,
    float* __restrict__ out, int E)
{
    int w = (blockIdx.x * 256 + threadIdx.x) >> 5;
    if (w >= E) return;
    int lane = threadIdx.x & 31;
    int r = __ldg(rows + w);
    int c = __ldg(cols + w);
    float4 kv = ((const float4*)g_kact)[r];
    float4 qv = ((const float4*)g_qagg)[c];
    uint4  mu = ((const uint4*)g_mx)[r];
    float4 sv = ((const float4*)g_sm)[r];
    float a = __expf(kv.x * qv.x - unflipf(mu.x)) * __fdividef(1.0f, sv.x + 1e-8f)
            + __expf(kv.y * qv.y - unflipf(mu.y)) * __fdividef(1.0f, sv.y + 1e-8f)
            + __expf(kv.z * qv.z - unflipf(mu.z)) * __fdividef(1.0f, sv.z + 1e-8f)
            + __expf(kv.w * qv.w - unflipf(mu.w)) * __fdividef(1.0f, sv.w + 1e-8f);
    a *= 0.25f;
    float4 v = ((const float4*)g_hproj)[(size_t)c * (OUT_DIM / 4) + lane];
    float* p = out + (size_t)r * OUT_DIM + lane * 4;
    red_add_v4(p, a * v.x, a * v.y, a * v.z, a * v.w);
}

// ================= kernel 6: final leaky relu =================
__global__ __launch_bounds__(256) void leaky_kernel(float* __restrict__ out, int n4) {
    int i = blockIdx.x * 256 + threadIdx.x;
    if (i >= n4) return;
    float4 v = ((float4*)out)[i];
    v.x = (v.x >= 0.0f) ? v.x : NEG_SLOPE * v.x;
    v.y = (v.y >= 0.0f) ? v.y : NEG_SLOPE * v.y;
    v.z = (v.z >= 0.0f) ? v.z : NEG_SLOPE * v.z;
    v.w = (v.w >= 0.0f) ? v.w : NEG_SLOPE * v.w;
    ((float4*)out)[i] = v;
}

// ================= launch =================
extern "C" void kernel_launch(void* const* d_in, const int* in_sizes, int n_in,
                              void* d_out, int out_size)
{
    const float* x  = (const float*)d_in[0];
    const int*   ei = (const int*)d_in[1];
    const float* Wq = (const float*)d_in[2];
    const float* Wk = (const float*)d_in[3];
    const float* Wl = (const float*)d_in[4];
    const float* bl = (const float*)d_in[5];
    float* out = (float*)d_out;

    const int N = in_sizes[0] / IN_DIM;
    const int E = in_sizes[1] / 2;
    const int* rows = ei;
    const int* cols = ei + E;
    const int nh = N * NHEADS;

    // 0: init accumulators + zero output
    {
        int n = out_size > nh ? out_size : nh;
        init_kernel<<<(n + 255) / 256, 256>>>(out, out_size, nh);
    }
    // 1: projections
    proj_kernel<<<(N + NPB - 1) / NPB, 128>>>(x, Wq, Wk, Wl, bl, N);
    // 2: q aggregation
    qagg_kernel<<<(E + 255) / 256, 256>>>(rows, cols, E);
    // 3: segment max
    smax_kernel<<<(E + 255) / 256, 256>>>(rows, cols, E);
    // 4: segment sum of exp
    ssum_kernel<<<(E + 255) / 256, 256>>>(rows, cols, E);
    // 5: weighted aggregation (warp per edge)
    {
        long long threads = (long long)E * 32;
        int blocks = (int)((threads + 255) / 256);
        aggregate_kernel<<<blocks, 256>>>(rows, cols, out, E);
    }
    // 6: final leaky relu
    leaky_kernel<<<(out_size / 4 + 255) / 256, 256>>>(out, out_size / 4);
}

// round 2
// speedup vs baseline: 2.4928x; 2.4928x over previous
#include <cuda_runtime.h>
#include <cuda_bf16.h>
#include <cstdint>

#define IN_DIM  128
#define OUT_DIM 128
#define NHEADS  4
#define NEG_SLOPE 0.2f

#define N_MAX 50000
#define E_MAX 1600000
#define FULL 0xFFFFFFFFu

// -------- device scratch (static: no allocation allowed) --------
__device__ float g_hq   [N_MAX * NHEADS];
__device__ float g_kact [N_MAX * NHEADS];
__device__ float g_qagg [N_MAX * NHEADS];
__device__ float g_hproj[(size_t)N_MAX * OUT_DIM];
__device__ int   g_cnt  [N_MAX];
__device__ int   g_off  [N_MAX + 1];
__device__ int   g_pos  [N_MAX];
__device__ int   g_bsum [256];
__device__ int   g_csr_col[E_MAX];

// ================= kernel 0: init (zero histogram) =================
__global__ __launch_bounds__(256) void init_kernel(int N) {
    int i = blockIdx.x * 256 + threadIdx.x;
    if (i < N) g_cnt[i] = 0;
}

// ================= kernel 1: projections =================
#define NPB 16
__global__ __launch_bounds__(128) void proj_kernel(
    const float* __restrict__ x,
    const float* __restrict__ Wq, const float* __restrict__ Wk,
    const float* __restrict__ Wl, const float* __restrict__ bl, int N)
{
    __shared__ float xs[NPB * IN_DIM];
    const int t = threadIdx.x;
    const int base = blockIdx.x * NPB;
    const int nn = min(NPB, N - base);
    if (nn <= 0) return;

    {
        const float4* xg = (const float4*)(x + (size_t)base * IN_DIM);
        float4* xs4 = (float4*)xs;
        const int tot4 = nn * (IN_DIM / 4);
        for (int i = t; i < tot4; i += 128) xs4[i] = xg[i];
    }
    __syncthreads();

    // per-head q/k projections: t = n2*8 + h
    {
        const int n2 = t >> 3;
        const int h  = t & 7;
        if (n2 < nn) {
            const float* wrow = (h < 4) ? (Wq + h * IN_DIM) : (Wk + (h - 4) * IN_DIM);
            const float4* w4 = (const float4*)wrow;
            const float4* xr = (const float4*)(xs + n2 * IN_DIM);
            float d = 0.0f;
            #pragma unroll
            for (int k = 0; k < IN_DIM / 4; k++) {
                float4 w = w4[k]; float4 xv = xr[k];
                d += w.x * xv.x + w.y * xv.y + w.z * xv.z + w.w * xv.w;
            }
            const int node = base + n2;
            if (h < 4) g_hq[node * NHEADS + h] = d;
            else       g_kact[node * NHEADS + (h - 4)] = (d >= 0.0f) ? d : NEG_SLOPE * d;
        }
    }

    float acc[NPB];
    #pragma unroll
    for (int n = 0; n < NPB; n++) acc[n] = 0.0f;

    const float4* wl4 = (const float4*)(Wl + (size_t)t * IN_DIM);
    #pragma unroll 4
    for (int k = 0; k < IN_DIM / 4; k++) {
        float4 w = wl4[k];
        #pragma unroll
        for (int n = 0; n < NPB; n++) {
            float4 xv = ((const float4*)(xs + n * IN_DIM))[k];
            acc[n] += w.x * xv.x + w.y * xv.y + w.z * xv.z + w.w * xv.w;
        }
    }
    const float b = bl[t];
    for (int n = 0; n < nn; n++)
        g_hproj[(size_t)(base + n) * OUT_DIM + t] = acc[n] + b;
}

// ================= kernel 2: histogram of rows =================
__global__ __launch_bounds__(256) void hist_kernel(const int* __restrict__ rows, int E) {
    int e = blockIdx.x * 256 + threadIdx.x;
    if (e < E) atomicAdd(&g_cnt[rows[e]], 1);
}

// ================= scan (3 stages) =================
__device__ __forceinline__ int warp_incl_scan(int v, int lane) {
    #pragma unroll
    for (int d = 1; d < 32; d <<= 1) {
        int t = __shfl_up_sync(FULL, v, d);
        if (lane >= d) v += t;
    }
    return v;
}

__global__ __launch_bounds__(256) void scan1_kernel(int N) {
    int i = blockIdx.x * 256 + threadIdx.x;
    int lane = threadIdx.x & 31, wid = threadIdx.x >> 5;
    int v = (i < N) ? g_cnt[i] : 0;
    int s = warp_incl_scan(v, lane);
    __shared__ int wsum[8];
    if (lane == 31) wsum[wid] = s;
    __syncthreads();
    if (wid == 0) {
        int ws = (lane < 8) ? wsum[lane] : 0;
        #pragma unroll
        for (int d = 1; d < 8; d <<= 1) {
            int t = __shfl_up_sync(FULL, ws, d);
            if (lane >= d) ws += t;
        }
        if (lane < 8) wsum[lane] = ws;
    }
    __syncthreads();
    int excl = s - v + (wid > 0 ? wsum[wid - 1] : 0);
    if (i < N) g_off[i] = excl;
    if (threadIdx.x == 255) g_bsum[blockIdx.x] = excl + v; // block total
}

__global__ __launch_bounds__(256) void scan2_kernel(int nb) {
    int i = threadIdx.x;
    int lane = i & 31, wid = i >> 5;
    int v = (i < nb) ? g_bsum[i] : 0;
    int s = warp_incl_scan(v, lane);
    __shared__ int wsum[8];
    if (lane == 31) wsum[wid] = s;
    __syncthreads();
    if (wid == 0) {
        int ws = (lane < 8) ? wsum[lane] : 0;
        #pragma unroll
        for (int d = 1; d < 8; d <<= 1) {
            int t = __shfl_up_sync(FULL, ws, d);
            if (lane >= d) ws += t;
        }
        if (lane < 8) wsum[lane] = ws;
    }
    __syncthreads();
    int excl = s - v + (wid > 0 ? wsum[wid - 1] : 0);
    if (i < nb) g_bsum[i] = excl;
}

__global__ __launch_bounds__(256) void scan3_kernel(int N, int E) {
    int i = blockIdx.x * 256 + threadIdx.x;
    if (i < N) {
        int o = g_off[i] + g_bsum[i >> 8];
        g_off[i] = o;
        g_pos[i] = o;
    }
    if (i == 0) g_off[N] = E;
}

// ================= kernel: scatter edges into CSR =================
__global__ __launch_bounds__(256) void scatter_kernel(
    const int* __restrict__ rows, const int* __restrict__ cols, int E)
{
    int e = blockIdx.x * 256 + threadIdx.x;
    if (e >= E) return;
    int r = rows[e];
    int p = atomicAdd(&g_pos[r], 1);
    g_csr_col[p] = cols[e];
}

// ================= kernel: q_agg via CSR (no atomics) =================
__global__ __launch_bounds__(256) void qagg_csr_kernel(int N) {
    int w = (blockIdx.x * 256 + threadIdx.x) >> 5;
    int lane = threadIdx.x & 31;
    if (w >= N) return;
    int beg = g_off[w], end = g_off[w + 1];
    float4 acc = {0.f, 0.f, 0.f, 0.f};
    for (int e = beg + lane; e < end; e += 32) {
        int c = __ldg(g_csr_col + e);
        float4 v = __ldg(((const float4*)g_hq) + c);
        acc.x += v.x; acc.y += v.y; acc.z += v.z; acc.w += v.w;
    }
    #pragma unroll
    for (int d = 16; d; d >>= 1) {
        acc.x += __shfl_xor_sync(FULL, acc.x, d);
        acc.y += __shfl_xor_sync(FULL, acc.y, d);
        acc.z += __shfl_xor_sync(FULL, acc.z, d);
        acc.w += __shfl_xor_sync(FULL, acc.w, d);
    }
    if (lane == 0) ((float4*)g_qagg)[w] = acc;
}

// ================= fused attention + aggregation (warp per node) ======
__global__ __launch_bounds__(256) void attn_agg_kernel(float* __restrict__ out, int N) {
    int node = (blockIdx.x * 256 + threadIdx.x) >> 5;
    int lane = threadIdx.x & 31;
    if (node >= N) return;
    const int beg = g_off[node], end = g_off[node + 1];
    const int deg = end - beg;

    float4* outp = ((float4*)out) + (size_t)node * (OUT_DIM / 4) + lane;
    if (deg == 0) { float4 z = {0.f,0.f,0.f,0.f}; *outp = z; return; }

    const float4 ka = ((const float4*)g_kact)[node];

    // pass 1: per-head max
    float4 mx = {-3.4e38f, -3.4e38f, -3.4e38f, -3.4e38f};
    for (int e = beg + lane; e < end; e += 32) {
        int c = __ldg(g_csr_col + e);
        float4 q = __ldg(((const float4*)g_qagg) + c);
        mx.x = fmaxf(mx.x, ka.x * q.x);
        mx.y = fmaxf(mx.y, ka.y * q.y);
        mx.z = fmaxf(mx.z, ka.z * q.z);
        mx.w = fmaxf(mx.w, ka.w * q.w);
    }
    #pragma unroll
    for (int d = 16; d; d >>= 1) {
        mx.x = fmaxf(mx.x, __shfl_xor_sync(FULL, mx.x, d));
        mx.y = fmaxf(mx.y, __shfl_xor_sync(FULL, mx.y, d));
        mx.z = fmaxf(mx.z, __shfl_xor_sync(FULL, mx.z, d));
        mx.w = fmaxf(mx.w, __shfl_xor_sync(FULL, mx.w, d));
    }

    // pass 2: per-head sum of exp
    float4 sm = {0.f, 0.f, 0.f, 0.f};
    for (int e = beg + lane; e < end; e += 32) {
        int c = __ldg(g_csr_col + e);
        float4 q = __ldg(((const float4*)g_qagg) + c);
        sm.x += __expf(ka.x * q.x - mx.x);
        sm.y += __expf(ka.y * q.y - mx.y);
        sm.z += __expf(ka.z * q.z - mx.z);
        sm.w += __expf(ka.w * q.w - mx.w);
    }
    #pragma unroll
    for (int d = 16; d; d >>= 1) {
        sm.x += __shfl_xor_sync(FULL, sm.x, d);
        sm.y += __shfl_xor_sync(FULL, sm.y, d);
        sm.z += __shfl_xor_sync(FULL, sm.z, d);
        sm.w += __shfl_xor_sync(FULL, sm.w, d);
    }
    float4 inv;
    inv.x = 0.25f * __fdividef(1.0f, sm.x + 1e-8f);
    inv.y = 0.25f * __fdividef(1.0f, sm.y + 1e-8f);
    inv.z = 0.25f * __fdividef(1.0f, sm.z + 1e-8f);
    inv.w = 0.25f * __fdividef(1.0f, sm.w + 1e-8f);

    // pass 3: alpha per edge (32 at a time), broadcast + accumulate
    float4 acc = {0.f, 0.f, 0.f, 0.f};
    for (int base = beg; base < end; base += 32) {
        int e = base + lane;
        float a = 0.0f;
        int c = 0;
        if (e < end) {
            c = __ldg(g_csr_col + e);
            float4 q = __ldg(((const float4*)g_qagg) + c);
            a = __expf(ka.x * q.x - mx.x) * inv.x
              + __expf(ka.y * q.y - mx.y) * inv.y
              + __expf(ka.z * q.z - mx.z) * inv.z
              + __expf(ka.w * q.w - mx.w) * inv.w;
        }
        int cnt = min(32, end - base);
        if (cnt == 32) {
            #pragma unroll 8
            for (int j = 0; j < 32; j++) {
                float aj = __shfl_sync(FULL, a, j);
                int   cj = __shfl_sync(FULL, c, j);
                float4 v = __ldg(((const float4*)g_hproj) + (size_t)cj * (OUT_DIM / 4) + lane);
                acc.x += aj * v.x; acc.y += aj * v.y; acc.z += aj * v.z; acc.w += aj * v.w;
            }
        } else {
            for (int j = 0; j < cnt; j++) {
                float aj = __shfl_sync(FULL, a, j);
                int   cj = __shfl_sync(FULL, c, j);
                float4 v = __ldg(((const float4*)g_hproj) + (size_t)cj * (OUT_DIM / 4) + lane);
                acc.x += aj * v.x; acc.y += aj * v.y; acc.z += aj * v.z; acc.w += aj * v.w;
            }
        }
    }

    // fused final leaky relu + single coalesced write
    acc.x = (acc.x >= 0.f) ? acc.x : NEG_SLOPE * acc.x;
    acc.y = (acc.y >= 0.f) ? acc.y : NEG_SLOPE * acc.y;
    acc.z = (acc.z >= 0.f) ? acc.z : NEG_SLOPE * acc.z;
    acc.w = (acc.w >= 0.f) ? acc.w : NEG_SLOPE * acc.w;
    *outp = acc;
}

// ================= launch =================
extern "C" void kernel_launch(void* const* d_in, const int* in_sizes, int n_in,
                              void* d_out, int out_size)
{
    const float* x  = (const float*)d_in[0];
    const int*   ei = (const int*)d_in[1];
    const float* Wq = (const float*)d_in[2];
    const float* Wk = (const float*)d_in[3];
    const float* Wl = (const float*)d_in[4];
    const float* bl = (const float*)d_in[5];
    float* out = (float*)d_out;

    const int N = in_sizes[0] / IN_DIM;
    const int E = in_sizes[1] / 2;
    const int* rows = ei;
    const int* cols = ei + E;
    const int nblocksN = (N + 255) / 256;

    init_kernel<<<nblocksN, 256>>>(N);
    proj_kernel<<<(N + NPB - 1) / NPB, 128>>>(x, Wq, Wk, Wl, bl, N);
    hist_kernel<<<(E + 255) / 256, 256>>>(rows, E);
    scan1_kernel<<<nblocksN, 256>>>(N);
    scan2_kernel<<<1, 256>>>(nblocksN);
    scan3_kernel<<<nblocksN, 256>>>(N, E);
    scatter_kernel<<<(E + 255) / 256, 256>>>(rows, cols, E);
    qagg_csr_kernel<<<(N * 32 + 255) / 256, 256>>>(N);
    attn_agg_kernel<<<(N * 32 + 255) / 256, 256>>>(out, N);
}